// round 4
// baseline (speedup 1.0000x reference)
#include <cuda_runtime.h>
#include <cuda_bf16.h>
#include <cstdint>
#include <cstddef>

#define HID        256
#define NNODES     50000
#define NEDGES     800000
#define NROWS_LBL  8192

// ---------------- scratch (allocation-free rule) ----------------
__device__ float g_h [(size_t)NNODES * HID];
__device__ float g_x [(size_t)NNODES * HID];
__device__ __nv_bfloat16 g_xh[(size_t)NNODES * HID];
__device__ __nv_bfloat16 g_xl[(size_t)NNODES * HID];
__device__ __nv_bfloat16 g_yh[(size_t)NNODES * HID];
__device__ __nv_bfloat16 g_yl[(size_t)NNODES * HID];
__device__ __nv_bfloat16 g_wth[9 * 65536];
__device__ __nv_bfloat16 g_wtl[9 * 65536];
__device__ int g_cnt[NNODES];
__device__ int g_off[NNODES + 1];
__device__ int g_eid[NEDGES];

// ---------------- mma.sync bf16 split GEMM ----------------
#define KC      32
#define LDS_A   40          // halves; 80B row stride -> conflict-free
#define TILE_HB (128 * LDS_A * 2)   // bytes per tile (10240)
#define STAGE_B (4 * TILE_HB)       // Ah Al Bh Bl  (40960)

__device__ __forceinline__ void mma16816(float* c, const uint32_t* a, const uint32_t* b)
{
    asm volatile(
        "mma.sync.aligned.m16n8k16.row.col.f32.bf16.bf16.f32 "
        "{%0,%1,%2,%3}, {%4,%5,%6,%7}, {%8,%9}, {%0,%1,%2,%3};"
        : "+f"(c[0]), "+f"(c[1]), "+f"(c[2]), "+f"(c[3])
        : "r"(a[0]), "r"(a[1]), "r"(a[2]), "r"(a[3]), "r"(b[0]), "r"(b[1]));
}

__device__ __forceinline__ void cpa16(uint32_t dst, const void* src, int sz)
{
    asm volatile("cp.async.ca.shared.global [%0], [%1], 16, %2;"
                 :: "r"(dst), "l"(src), "r"(sz));
}
__device__ __forceinline__ void cpa_commit() {
    asm volatile("cp.async.commit_group;");
}
template <int N>
__device__ __forceinline__ void cpa_wait() {
    asm volatile("cp.async.wait_group %0;" :: "n"(N));
}

// out_mode 0: C fp32 = acc + bias
// out_mode 1: (Oh,Ol) bf16 hi/lo pair of (acc + bias)
__global__ __launch_bounds__(256, 2)
void tc_gemm(const __nv_bfloat16* __restrict__ Ah, const __nv_bfloat16* __restrict__ Al,
             const __nv_bfloat16* __restrict__ Wth, const __nv_bfloat16* __restrict__ Wtl,
             const float* __restrict__ bias,
             float* __restrict__ C,
             __nv_bfloat16* __restrict__ Oh, __nv_bfloat16* __restrict__ Ol,
             int M, const int* __restrict__ rowmap, int out_mode)
{
    extern __shared__ __align__(16) char smem_dyn[];

    const int tid  = threadIdx.x;
    const int wid  = tid >> 5;
    const int lane = tid & 31;
    const int bm   = blockIdx.x * 128;
    const int bn   = blockIdx.y * 128;
    const int wr   = wid & 1;
    const int wc   = wid >> 1;
    const int qp = lane >> 2;
    const int qr = lane & 3;

    const uint32_t smem_u = (uint32_t)__cvta_generic_to_shared(smem_dyn);

    float acc[4][4][4];
#pragma unroll
    for (int i = 0; i < 4; i++)
#pragma unroll
        for (int j = 0; j < 4; j++)
#pragma unroll
            for (int r = 0; r < 4; r++) acc[i][j][r] = 0.f;

    // rows this thread stages (2 x 16B per matrix per chunk)
    int arow[2];
#pragma unroll
    for (int i = 0; i < 2; i++) {
        int u = i * 256 + tid;
        int r = u >> 2;
        int grow = bm + r;
        arow[i] = rowmap ? __ldg(&rowmap[grow]) : (grow < M ? grow : -1);
    }

    // ---- async stage loader ----
    auto load_stage = [&](int st, int k0) {
        const uint32_t sb = smem_u + st * STAGE_B;
#pragma unroll
        for (int i = 0; i < 2; i++) {
            int u = i * 256 + tid;
            int r = u >> 2;
            int cq = (u & 3);             // 16B quarter within 64B row
            uint32_t doff = (uint32_t)(r * (LDS_A * 2) + cq * 16);
            int khalf = k0 + cq * 8;
            int sz = (arow[i] >= 0) ? 16 : 0;
            const __nv_bfloat16* gh = Ah + ((size_t)(arow[i] >= 0 ? arow[i] : 0)) * HID + khalf;
            const __nv_bfloat16* gl = Al + ((size_t)(arow[i] >= 0 ? arow[i] : 0)) * HID + khalf;
            cpa16(sb + 0 * TILE_HB + doff, gh, sz);
            cpa16(sb + 1 * TILE_HB + doff, gl, sz);
            cpa16(sb + 2 * TILE_HB + doff,
                  Wth + (size_t)(bn + r) * HID + khalf, 16);
            cpa16(sb + 3 * TILE_HB + doff,
                  Wtl + (size_t)(bn + r) * HID + khalf, 16);
        }
    };

    // ---- compute on a staged buffer ----
    auto compute_stage = [&](int st) {
        const __nv_bfloat16* sAh = (const __nv_bfloat16*)(smem_dyn + st * STAGE_B + 0 * TILE_HB);
        const __nv_bfloat16* sAl = (const __nv_bfloat16*)(smem_dyn + st * STAGE_B + 1 * TILE_HB);
        const __nv_bfloat16* sBh = (const __nv_bfloat16*)(smem_dyn + st * STAGE_B + 2 * TILE_HB);
        const __nv_bfloat16* sBl = (const __nv_bfloat16*)(smem_dyn + st * STAGE_B + 3 * TILE_HB);
#pragma unroll
        for (int ks = 0; ks < KC; ks += 16) {
            uint32_t fAh[4][4], fAl[4][4];
#pragma unroll
            for (int mt = 0; mt < 4; mt++) {
                int r0 = wr * 64 + mt * 16 + qp;
                int kk = ks + qr * 2;
                const __nv_bfloat16* ph = sAh + r0 * LDS_A + kk;
                const __nv_bfloat16* pl = sAl + r0 * LDS_A + kk;
                fAh[mt][0] = *(const uint32_t*)(ph);
                fAh[mt][1] = *(const uint32_t*)(ph + 8 * LDS_A);
                fAh[mt][2] = *(const uint32_t*)(ph + 8);
                fAh[mt][3] = *(const uint32_t*)(ph + 8 * LDS_A + 8);
                fAl[mt][0] = *(const uint32_t*)(pl);
                fAl[mt][1] = *(const uint32_t*)(pl + 8 * LDS_A);
                fAl[mt][2] = *(const uint32_t*)(pl + 8);
                fAl[mt][3] = *(const uint32_t*)(pl + 8 * LDS_A + 8);
            }
            {
                uint32_t fB[4][2];
#pragma unroll
                for (int nt = 0; nt < 4; nt++) {
                    int n0 = wc * 32 + nt * 8 + qp;
                    int kk = ks + qr * 2;
                    const __nv_bfloat16* pb = sBh + n0 * LDS_A + kk;
                    fB[nt][0] = *(const uint32_t*)(pb);
                    fB[nt][1] = *(const uint32_t*)(pb + 8);
                }
#pragma unroll
                for (int mt = 0; mt < 4; mt++)
#pragma unroll
                    for (int nt = 0; nt < 4; nt++) {
                        mma16816(acc[mt][nt], fAh[mt], fB[nt]);
                        mma16816(acc[mt][nt], fAl[mt], fB[nt]);
                    }
            }
            {
                uint32_t fB[4][2];
#pragma unroll
                for (int nt = 0; nt < 4; nt++) {
                    int n0 = wc * 32 + nt * 8 + qp;
                    int kk = ks + qr * 2;
                    const __nv_bfloat16* pb = sBl + n0 * LDS_A + kk;
                    fB[nt][0] = *(const uint32_t*)(pb);
                    fB[nt][1] = *(const uint32_t*)(pb + 8);
                }
#pragma unroll
                for (int mt = 0; mt < 4; mt++)
#pragma unroll
                    for (int nt = 0; nt < 4; nt++)
                        mma16816(acc[mt][nt], fAh[mt], fB[nt]);
            }
        }
    };

    // ---- pipelined K loop (8 chunks, 2 stages) ----
    load_stage(0, 0);
    cpa_commit();
#pragma unroll
    for (int c = 0; c < 8; c++) {
        if (c < 7) {
            load_stage((c + 1) & 1, (c + 1) * KC);
            cpa_commit();
            cpa_wait<1>();
        } else {
            cpa_wait<0>();
        }
        __syncthreads();
        compute_stage(c & 1);
        __syncthreads();
    }

    // ---- epilogue ----
#pragma unroll
    for (int mt = 0; mt < 4; mt++) {
        int grow0 = bm + wr * 64 + mt * 16 + qp;
        int grow1 = grow0 + 8;
        int row0 = rowmap ? __ldg(&rowmap[grow0]) : grow0;
        int row1 = rowmap ? __ldg(&rowmap[grow1]) : grow1;
        bool v0 = rowmap ? true : (grow0 < M);
        bool v1 = rowmap ? true : (grow1 < M);
#pragma unroll
        for (int nt = 0; nt < 4; nt++) {
            int col = bn + wc * 32 + nt * 8 + qr * 2;
            float b0 = __ldg(&bias[col]);
            float b1 = __ldg(&bias[col + 1]);
            float o00 = acc[mt][nt][0] + b0, o01 = acc[mt][nt][1] + b1;
            float o10 = acc[mt][nt][2] + b0, o11 = acc[mt][nt][3] + b1;
            if (out_mode == 0) {
                if (v0) *(float2*)(C + (size_t)row0 * HID + col) = make_float2(o00, o01);
                if (v1) *(float2*)(C + (size_t)row1 * HID + col) = make_float2(o10, o11);
            } else {
                __nv_bfloat16 h00 = __float2bfloat16(o00), h01 = __float2bfloat16(o01);
                __nv_bfloat16 h10 = __float2bfloat16(o10), h11 = __float2bfloat16(o11);
                __nv_bfloat162 hp0(h00, h01), hp1(h10, h11);
                __nv_bfloat162 lp0(__float2bfloat16(o00 - __bfloat162float(h00)),
                                   __float2bfloat16(o01 - __bfloat162float(h01)));
                __nv_bfloat162 lp1(__float2bfloat16(o10 - __bfloat162float(h10)),
                                   __float2bfloat16(o11 - __bfloat162float(h11)));
                if (v0) {
                    *(__nv_bfloat162*)(Oh + (size_t)row0 * HID + col) = hp0;
                    *(__nv_bfloat162*)(Ol + (size_t)row0 * HID + col) = lp0;
                }
                if (v1) {
                    *(__nv_bfloat162*)(Oh + (size_t)row1 * HID + col) = hp1;
                    *(__nv_bfloat162*)(Ol + (size_t)row1 * HID + col) = lp1;
                }
            }
        }
    }
}

// ---------------- fp32 -> bf16 hi/lo pair (input x only) ----------------
__global__ void to_pair(const float* __restrict__ in,
                        __nv_bfloat16* __restrict__ hi, __nv_bfloat16* __restrict__ lo,
                        int n4)
{
    int t = blockIdx.x * blockDim.x + threadIdx.x;
    if (t >= n4) return;
    float4 v = ((const float4*)in)[t];
    __nv_bfloat16 h0 = __float2bfloat16(v.x);
    __nv_bfloat16 h1 = __float2bfloat16(v.y);
    __nv_bfloat16 h2 = __float2bfloat16(v.z);
    __nv_bfloat16 h3 = __float2bfloat16(v.w);
    __nv_bfloat162 hp0(h0, h1), hp1(h2, h3);
    __nv_bfloat162 lp0(__float2bfloat16(v.x - __bfloat162float(h0)),
                       __float2bfloat16(v.y - __bfloat162float(h1)));
    __nv_bfloat162 lp1(__float2bfloat16(v.z - __bfloat162float(h2)),
                       __float2bfloat16(v.w - __bfloat162float(h3)));
    ((__nv_bfloat162*)hi)[t * 2 + 0] = hp0;
    ((__nv_bfloat162*)hi)[t * 2 + 1] = hp1;
    ((__nv_bfloat162*)lo)[t * 2 + 0] = lp0;
    ((__nv_bfloat162*)lo)[t * 2 + 1] = lp1;
}

// ---------------- weight transpose + split ----------------
__global__ void transpose_w(const float* __restrict__ f0w, const float* __restrict__ f1w,
                            const float* __restrict__ cw,
                            __nv_bfloat16* __restrict__ wth, __nv_bfloat16* __restrict__ wtl)
{
    __shared__ float tileS[32][33];
    const int m = blockIdx.y;
    const int layer = m / 3, which = m % 3;
    const float* src = (which == 0 ? f0w : which == 1 ? f1w : cw) + (size_t)layer * 65536;
    const int tk = (blockIdx.x & 7) * 32;
    const int tn = (blockIdx.x >> 3) * 32;
    const int tx = threadIdx.x, ty = threadIdx.y;
#pragma unroll
    for (int r = 0; r < 4; r++)
        tileS[ty + r * 8][tx] = src[(tk + ty + r * 8) * 256 + tn + tx];
    __syncthreads();
#pragma unroll
    for (int r = 0; r < 4; r++) {
        int n = tn + ty + r * 8;
        int k = tk + tx;
        float v = tileS[tx][ty + r * 8];
        __nv_bfloat16 h = __float2bfloat16(v);
        __nv_bfloat16 l = __float2bfloat16(v - __bfloat162float(h));
        wth[(size_t)m * 65536 + n * 256 + k] = h;
        wtl[(size_t)m * 65536 + n * 256 + k] = l;
    }
}

// ---------------- CSR build ----------------
__global__ void csr_zero(int* __restrict__ cnt)
{
    int t = blockIdx.x * blockDim.x + threadIdx.x;
    if (t < NNODES) cnt[t] = 0;
}
__global__ void csr_hist(const int* __restrict__ dst, int* __restrict__ cnt)
{
    int t = blockIdx.x * blockDim.x + threadIdx.x;
    if (t < NEDGES) atomicAdd(&cnt[__ldg(&dst[t])], 1);
}
__global__ __launch_bounds__(1024)
void csr_scan(int* __restrict__ cnt, int* __restrict__ off)
{
    __shared__ int part[1024];
    const int tid = threadIdx.x;
    const int base = tid * 49;
    int s = 0;
    for (int i = 0; i < 49; i++) {
        int idx = base + i;
        if (idx < NNODES) s += cnt[idx];
    }
    part[tid] = s;
    __syncthreads();
    int mine = s;
    for (int d = 1; d < 1024; d <<= 1) {
        int v = (tid >= d) ? part[tid - d] : 0;
        __syncthreads();
        part[tid] += v;
        __syncthreads();
    }
    int run = part[tid] - mine;       // exclusive prefix
    for (int i = 0; i < 49; i++) {
        int idx = base + i;
        if (idx < NNODES) {
            off[idx] = run;
            run += cnt[idx];
            cnt[idx] = 0;             // reset as fill cursor
        }
    }
    if (tid == 1023) off[NNODES] = run;
}
__global__ void csr_fill(const int* __restrict__ src, const int* __restrict__ dst,
                         const int* __restrict__ off, int* __restrict__ cur,
                         int* __restrict__ eid)
{
    int t = blockIdx.x * blockDim.x + threadIdx.x;
    if (t >= NEDGES) return;
    int d = __ldg(&dst[t]);
    int p = atomicAdd(&cur[d], 1);
    eid[__ldg(&off[d]) + p] = __ldg(&src[t]);
}

// ---------------- pull segment-sum (+ fused split) ----------------
__global__ __launch_bounds__(256)
void pull_sum(const float* __restrict__ h, const int* __restrict__ off,
              const int* __restrict__ eid, float* __restrict__ xc,
              __nv_bfloat16* __restrict__ xh, __nv_bfloat16* __restrict__ xl)
{
    int node = blockIdx.x * 8 + (threadIdx.x >> 5);
    if (node >= NNODES) return;
    int lane = threadIdx.x & 31;
    int s0 = __ldg(&off[node]);
    int s1 = __ldg(&off[node + 1]);
    float4 a0 = make_float4(0.f, 0.f, 0.f, 0.f), a1 = a0;
    const float4* H = (const float4*)h;
    int i = s0;
    for (; i + 1 < s1; i += 2) {
        int e0 = __ldg(&eid[i]);
        int e1 = __ldg(&eid[i + 1]);
        const float4* r0 = H + (size_t)e0 * 64 + lane * 2;
        const float4* r1 = H + (size_t)e1 * 64 + lane * 2;
        float4 v00 = __ldg(r0), v01 = __ldg(r0 + 1);
        float4 v10 = __ldg(r1), v11 = __ldg(r1 + 1);
        a0.x += v00.x; a0.y += v00.y; a0.z += v00.z; a0.w += v00.w;
        a1.x += v01.x; a1.y += v01.y; a1.z += v01.z; a1.w += v01.w;
        a0.x += v10.x; a0.y += v10.y; a0.z += v10.z; a0.w += v10.w;
        a1.x += v11.x; a1.y += v11.y; a1.z += v11.z; a1.w += v11.w;
    }
    if (i < s1) {
        int e0 = __ldg(&eid[i]);
        const float4* r0 = H + (size_t)e0 * 64 + lane * 2;
        float4 v00 = __ldg(r0), v01 = __ldg(r0 + 1);
        a0.x += v00.x; a0.y += v00.y; a0.z += v00.z; a0.w += v00.w;
        a1.x += v01.x; a1.y += v01.y; a1.z += v01.z; a1.w += v01.w;
    }
    // fp32 out
    float4* X = (float4*)xc + (size_t)node * 64 + lane * 2;
    X[0] = a0; X[1] = a1;
    // fused hi/lo split (8 values)
    float vals[8] = {a0.x, a0.y, a0.z, a0.w, a1.x, a1.y, a1.z, a1.w};
    __nv_bfloat16 hv[8], lv[8];
#pragma unroll
    for (int j = 0; j < 8; j++) {
        hv[j] = __float2bfloat16(vals[j]);
        lv[j] = __float2bfloat16(vals[j] - __bfloat162float(hv[j]));
    }
    *(uint4*)(xh + (size_t)node * HID + lane * 8) = *(uint4*)hv;
    *(uint4*)(xl + (size_t)node * HID + lane * 8) = *(uint4*)lv;
}

__global__ void gather_out(const float* __restrict__ x, const int* __restrict__ pos,
                           float4* __restrict__ out)
{
    int t = blockIdx.x * blockDim.x + threadIdx.x;
    if (t >= NROWS_LBL * 64) return;
    int r = t >> 6, c = t & 63;
    int row = __ldg(&pos[r]);
    out[t] = *(const float4*)(x + (size_t)row * HID + (c << 2));
}

// ---------------- launch ----------------
extern "C" void kernel_launch(void* const* d_in, const int* in_sizes, int n_in,
                              void* d_out, int out_size)
{
    (void)in_sizes; (void)n_in; (void)out_size;
    const float* x    = (const float*)d_in[0];
    const float* f0w  = (const float*)d_in[1];
    const float* f0b  = (const float*)d_in[2];
    const float* f1w  = (const float*)d_in[3];
    const float* f1b  = (const float*)d_in[4];
    const float* cw   = (const float*)d_in[5];
    const float* cb   = (const float*)d_in[6];
    const int*   esrc = (const int*)d_in[7];
    const int*   edst = (const int*)d_in[8];
    const int*   pos  = (const int*)d_in[9];

    float *h, *xc;
    __nv_bfloat16 *xh, *xl, *yh, *yl, *wth, *wtl;
    int *cnt, *off, *eid;
    cudaGetSymbolAddress((void**)&h,   g_h);
    cudaGetSymbolAddress((void**)&xc,  g_x);
    cudaGetSymbolAddress((void**)&xh,  g_xh);
    cudaGetSymbolAddress((void**)&xl,  g_xl);
    cudaGetSymbolAddress((void**)&yh,  g_yh);
    cudaGetSymbolAddress((void**)&yl,  g_yl);
    cudaGetSymbolAddress((void**)&wth, g_wth);
    cudaGetSymbolAddress((void**)&wtl, g_wtl);
    cudaGetSymbolAddress((void**)&cnt, g_cnt);
    cudaGetSymbolAddress((void**)&off, g_off);
    cudaGetSymbolAddress((void**)&eid, g_eid);

    const int SMEM_DYN = 2 * STAGE_B;   // 81920
    cudaFuncSetAttribute(tc_gemm, cudaFuncAttributeMaxDynamicSharedMemorySize, SMEM_DYN);

    const int n4 = NNODES * HID / 4;
    dim3 gN((NNODES + 127) / 128, 2);
    dim3 gL(NROWS_LBL / 128, 2);

    // weights + CSR (inputs are constant per call; rebuilt every call)
    transpose_w<<<dim3(64, 9), dim3(32, 8)>>>(f0w, f1w, cw, wth, wtl);
    csr_zero<<<(NNODES + 255) / 256, 256>>>(cnt);
    csr_hist<<<(NEDGES + 255) / 256, 256>>>(edst, cnt);
    csr_scan<<<1, 1024>>>(cnt, off);
    csr_fill<<<(NEDGES + 255) / 256, 256>>>(esrc, edst, off, cnt, eid);

    to_pair<<<(n4 + 255) / 256, 256>>>(x, xh, xl, n4);

    for (int i = 0; i < 3; i++) {
        const size_t wo = (size_t)i * 3 * 65536;
        // y = x @ f0_w + f0_b  (bf16 pair out)
        tc_gemm<<<gN, 256, SMEM_DYN>>>(xh, xl, wth + wo, wtl + wo,
                                       f0b + i * HID, nullptr, yh, yl,
                                       NNODES, nullptr, 1);
        // y[idx] = x[idx] @ f1_w + f1_b  (bf16 pair out)
        tc_gemm<<<gL, 256, SMEM_DYN>>>(xh, xl, wth + wo + 65536, wtl + wo + 65536,
                                       f1b + i * HID, nullptr, yh, yl,
                                       NROWS_LBL, pos, 1);
        // h = y @ conv_w + conv_b  (fp32 out)
        tc_gemm<<<gN, 256, SMEM_DYN>>>(yh, yl, wth + wo + 2 * 65536, wtl + wo + 2 * 65536,
                                       cb + i * HID, h, nullptr, nullptr,
                                       NNODES, nullptr, 0);
        // x = segment_sum(h[src], dst)  + fused split for next layer
        pull_sum<<<(NNODES + 7) / 8, 256>>>(h, off, eid, xc, xh, xl);
    }
    gather_out<<<(NROWS_LBL * 64 + 255) / 256, 256>>>(xc, pos, (float4*)d_out);
}

// round 5
// speedup vs baseline: 2.3099x; 2.3099x over previous
#include <cuda_runtime.h>
#include <cuda_bf16.h>
#include <cstdint>
#include <cstddef>

#define HID        256
#define NNODES     50000
#define NEDGES     800000
#define NROWS_LBL  8192
#define SCAN_BLKS  196            // ceil(50000/256)

// ---------------- scratch (allocation-free rule) ----------------
__device__ float g_h [(size_t)NNODES * HID];
__device__ float g_x [(size_t)NNODES * HID];
__device__ __nv_bfloat16 g_xh[(size_t)NNODES * HID];
__device__ __nv_bfloat16 g_xl[(size_t)NNODES * HID];
__device__ __nv_bfloat16 g_wth[6 * 65536];   // fused W^T [n][k], hi   (layer*2+which)
__device__ __nv_bfloat16 g_wtl[6 * 65536];   // fused W^T [n][k], lo
__device__ float g_beff[6 * 256];            // fused biases
__device__ int g_cnt[NNODES];
__device__ int g_off[NNODES + 1];
__device__ int g_eid[NEDGES];
__device__ int g_bsum[SCAN_BLKS];
__device__ int g_boff[SCAN_BLKS];

// ---------------- fused weight precompute ----------------
// Weff[k][n] = sum_t A[k][t] * Wc[t][n];  stored transposed+split:
// wth[m*65536 + n*256 + k]
__global__ __launch_bounds__(256)
void fuse_w(const float* __restrict__ f0w, const float* __restrict__ f1w,
            const float* __restrict__ cw,
            __nv_bfloat16* __restrict__ wth, __nv_bfloat16* __restrict__ wtl)
{
    __shared__ float sA[256];
    const int k = blockIdx.x;
    const int m = blockIdx.y;            // layer*2 + which
    const int layer = m >> 1, which = m & 1;
    const float* A  = (which == 0 ? f0w : f1w) + (size_t)layer * 65536;
    const float* Wc = cw + (size_t)layer * 65536;
    const int n = threadIdx.x;

    sA[n] = A[k * 256 + n];
    __syncthreads();

    float acc = 0.f;
#pragma unroll 8
    for (int t = 0; t < 256; t++)
        acc = fmaf(sA[t], __ldg(&Wc[t * 256 + n]), acc);

    __nv_bfloat16 h = __float2bfloat16(acc);
    __nv_bfloat16 l = __float2bfloat16(acc - __bfloat162float(h));
    wth[(size_t)m * 65536 + n * 256 + k] = h;
    wtl[(size_t)m * 65536 + n * 256 + k] = l;
}

// beff[m][n] = sum_t b[t] * Wc[t][n] + cb[n]
__global__ __launch_bounds__(256)
void fuse_b(const float* __restrict__ f0b, const float* __restrict__ f1b,
            const float* __restrict__ cw, const float* __restrict__ cb,
            float* __restrict__ beff)
{
    __shared__ float sB[256];
    const int m = blockIdx.x;
    const int layer = m >> 1, which = m & 1;
    const float* b  = (which == 0 ? f0b : f1b) + (size_t)layer * 256;
    const float* Wc = cw + (size_t)layer * 65536;
    const int n = threadIdx.x;
    sB[n] = b[n];
    __syncthreads();
    float acc = __ldg(&cb[layer * 256 + n]);
#pragma unroll 8
    for (int t = 0; t < 256; t++)
        acc = fmaf(sB[t], __ldg(&Wc[t * 256 + n]), acc);
    beff[m * 256 + n] = acc;
}

// ---------------- mma.sync bf16 split GEMM ----------------
#define KC      32
#define LDS_A   40
#define TILE_HB (128 * LDS_A * 2)
#define STAGE_B (4 * TILE_HB)

__device__ __forceinline__ void mma16816(float* c, const uint32_t* a, const uint32_t* b)
{
    asm volatile(
        "mma.sync.aligned.m16n8k16.row.col.f32.bf16.bf16.f32 "
        "{%0,%1,%2,%3}, {%4,%5,%6,%7}, {%8,%9}, {%0,%1,%2,%3};"
        : "+f"(c[0]), "+f"(c[1]), "+f"(c[2]), "+f"(c[3])
        : "r"(a[0]), "r"(a[1]), "r"(a[2]), "r"(a[3]), "r"(b[0]), "r"(b[1]));
}
__device__ __forceinline__ void cpa16(uint32_t dst, const void* src, int sz)
{
    asm volatile("cp.async.ca.shared.global [%0], [%1], 16, %2;"
                 :: "r"(dst), "l"(src), "r"(sz));
}
__device__ __forceinline__ void cpa_commit() { asm volatile("cp.async.commit_group;"); }
template <int N>
__device__ __forceinline__ void cpa_wait() {
    asm volatile("cp.async.wait_group %0;" :: "n"(N));
}

__global__ __launch_bounds__(256, 2)
void tc_gemm(const __nv_bfloat16* __restrict__ Ah, const __nv_bfloat16* __restrict__ Al,
             const __nv_bfloat16* __restrict__ Wth, const __nv_bfloat16* __restrict__ Wtl,
             const float* __restrict__ bias, float* __restrict__ C,
             int M, const int* __restrict__ rowmap)
{
    extern __shared__ __align__(16) char smem_dyn[];

    const int tid  = threadIdx.x;
    const int wid  = tid >> 5;
    const int lane = tid & 31;
    const int bm   = blockIdx.x * 128;
    const int bn   = blockIdx.y * 128;
    const int wr   = wid & 1;
    const int wc   = wid >> 1;
    const int qp = lane >> 2;
    const int qr = lane & 3;

    const uint32_t smem_u = (uint32_t)__cvta_generic_to_shared(smem_dyn);

    float acc[4][4][4];
#pragma unroll
    for (int i = 0; i < 4; i++)
#pragma unroll
        for (int j = 0; j < 4; j++)
#pragma unroll
            for (int r = 0; r < 4; r++) acc[i][j][r] = 0.f;

    int arow[2];
#pragma unroll
    for (int i = 0; i < 2; i++) {
        int u = i * 256 + tid;
        int r = u >> 2;
        int grow = bm + r;
        arow[i] = rowmap ? __ldg(&rowmap[grow]) : (grow < M ? grow : -1);
    }

    auto load_stage = [&](int st, int k0) {
        const uint32_t sb = smem_u + st * STAGE_B;
#pragma unroll
        for (int i = 0; i < 2; i++) {
            int u = i * 256 + tid;
            int r = u >> 2;
            int cq = (u & 3);
            uint32_t doff = (uint32_t)(r * (LDS_A * 2) + cq * 16);
            int khalf = k0 + cq * 8;
            int sz = (arow[i] >= 0) ? 16 : 0;
            const __nv_bfloat16* gh = Ah + ((size_t)(arow[i] >= 0 ? arow[i] : 0)) * HID + khalf;
            const __nv_bfloat16* gl = Al + ((size_t)(arow[i] >= 0 ? arow[i] : 0)) * HID + khalf;
            cpa16(sb + 0 * TILE_HB + doff, gh, sz);
            cpa16(sb + 1 * TILE_HB + doff, gl, sz);
            cpa16(sb + 2 * TILE_HB + doff, Wth + (size_t)(bn + r) * HID + khalf, 16);
            cpa16(sb + 3 * TILE_HB + doff, Wtl + (size_t)(bn + r) * HID + khalf, 16);
        }
    };

    auto compute_stage = [&](int st) {
        const __nv_bfloat16* sAh = (const __nv_bfloat16*)(smem_dyn + st * STAGE_B + 0 * TILE_HB);
        const __nv_bfloat16* sAl = (const __nv_bfloat16*)(smem_dyn + st * STAGE_B + 1 * TILE_HB);
        const __nv_bfloat16* sBh = (const __nv_bfloat16*)(smem_dyn + st * STAGE_B + 2 * TILE_HB);
        const __nv_bfloat16* sBl = (const __nv_bfloat16*)(smem_dyn + st * STAGE_B + 3 * TILE_HB);
#pragma unroll
        for (int ks = 0; ks < KC; ks += 16) {
            uint32_t fAh[4][4], fAl[4][4];
#pragma unroll
            for (int mt = 0; mt < 4; mt++) {
                int r0 = wr * 64 + mt * 16 + qp;
                int kk = ks + qr * 2;
                const __nv_bfloat16* ph = sAh + r0 * LDS_A + kk;
                const __nv_bfloat16* pl = sAl + r0 * LDS_A + kk;
                fAh[mt][0] = *(const uint32_t*)(ph);
                fAh[mt][1] = *(const uint32_t*)(ph + 8 * LDS_A);
                fAh[mt][2] = *(const uint32_t*)(ph + 8);
                fAh[mt][3] = *(const uint32_t*)(ph + 8 * LDS_A + 8);
                fAl[mt][0] = *(const uint32_t*)(pl);
                fAl[mt][1] = *(const uint32_t*)(pl + 8 * LDS_A);
                fAl[mt][2] = *(const uint32_t*)(pl + 8);
                fAl[mt][3] = *(const uint32_t*)(pl + 8 * LDS_A + 8);
            }
            {
                uint32_t fB[4][2];
#pragma unroll
                for (int nt = 0; nt < 4; nt++) {
                    int n0 = wc * 32 + nt * 8 + qp;
                    int kk = ks + qr * 2;
                    const __nv_bfloat16* pb = sBh + n0 * LDS_A + kk;
                    fB[nt][0] = *(const uint32_t*)(pb);
                    fB[nt][1] = *(const uint32_t*)(pb + 8);
                }
#pragma unroll
                for (int mt = 0; mt < 4; mt++)
#pragma unroll
                    for (int nt = 0; nt < 4; nt++) {
                        mma16816(acc[mt][nt], fAh[mt], fB[nt]);
                        mma16816(acc[mt][nt], fAl[mt], fB[nt]);
                    }
            }
            {
                uint32_t fB[4][2];
#pragma unroll
                for (int nt = 0; nt < 4; nt++) {
                    int n0 = wc * 32 + nt * 8 + qp;
                    int kk = ks + qr * 2;
                    const __nv_bfloat16* pb = sBl + n0 * LDS_A + kk;
                    fB[nt][0] = *(const uint32_t*)(pb);
                    fB[nt][1] = *(const uint32_t*)(pb + 8);
                }
#pragma unroll
                for (int mt = 0; mt < 4; mt++)
#pragma unroll
                    for (int nt = 0; nt < 4; nt++)
                        mma16816(acc[mt][nt], fAh[mt], fB[nt]);
            }
        }
    };

    load_stage(0, 0);
    cpa_commit();
#pragma unroll
    for (int c = 0; c < 8; c++) {
        if (c < 7) {
            load_stage((c + 1) & 1, (c + 1) * KC);
            cpa_commit();
            cpa_wait<1>();
        } else {
            cpa_wait<0>();
        }
        __syncthreads();
        compute_stage(c & 1);
        __syncthreads();
    }

#pragma unroll
    for (int mt = 0; mt < 4; mt++) {
        int grow0 = bm + wr * 64 + mt * 16 + qp;
        int grow1 = grow0 + 8;
        int row0 = rowmap ? __ldg(&rowmap[grow0]) : grow0;
        int row1 = rowmap ? __ldg(&rowmap[grow1]) : grow1;
        bool v0 = rowmap ? true : (grow0 < M);
        bool v1 = rowmap ? true : (grow1 < M);
#pragma unroll
        for (int nt = 0; nt < 4; nt++) {
            int col = bn + wc * 32 + nt * 8 + qr * 2;
            float b0 = __ldg(&bias[col]);
            float b1 = __ldg(&bias[col + 1]);
            if (v0) *(float2*)(C + (size_t)row0 * HID + col) =
                        make_float2(acc[mt][nt][0] + b0, acc[mt][nt][1] + b1);
            if (v1) *(float2*)(C + (size_t)row1 * HID + col) =
                        make_float2(acc[mt][nt][2] + b0, acc[mt][nt][3] + b1);
        }
    }
}

// ---------------- fp32 -> bf16 hi/lo pair (initial x only) ----------------
__global__ void to_pair(const float* __restrict__ in,
                        __nv_bfloat16* __restrict__ hi, __nv_bfloat16* __restrict__ lo,
                        int n4)
{
    int t = blockIdx.x * blockDim.x + threadIdx.x;
    if (t >= n4) return;
    float4 v = ((const float4*)in)[t];
    __nv_bfloat16 h0 = __float2bfloat16(v.x);
    __nv_bfloat16 h1 = __float2bfloat16(v.y);
    __nv_bfloat16 h2 = __float2bfloat16(v.z);
    __nv_bfloat16 h3 = __float2bfloat16(v.w);
    __nv_bfloat162 hp0(h0, h1), hp1(h2, h3);
    __nv_bfloat162 lp0(__float2bfloat16(v.x - __bfloat162float(h0)),
                       __float2bfloat16(v.y - __bfloat162float(h1)));
    __nv_bfloat162 lp1(__float2bfloat16(v.z - __bfloat162float(h2)),
                       __float2bfloat16(v.w - __bfloat162float(h3)));
    ((__nv_bfloat162*)hi)[t * 2 + 0] = hp0;
    ((__nv_bfloat162*)hi)[t * 2 + 1] = hp1;
    ((__nv_bfloat162*)lo)[t * 2 + 0] = lp0;
    ((__nv_bfloat162*)lo)[t * 2 + 1] = lp1;
}

// ---------------- CSR build (parallel scan) ----------------
__global__ void csr_zero(int* __restrict__ cnt)
{
    int t = blockIdx.x * blockDim.x + threadIdx.x;
    if (t < NNODES) cnt[t] = 0;
}
__global__ void csr_hist(const int* __restrict__ dst, int* __restrict__ cnt)
{
    int t = blockIdx.x * blockDim.x + threadIdx.x;
    if (t < NEDGES) atomicAdd(&cnt[__ldg(&dst[t])], 1);
}
// per-block exclusive scan of 256 counts; block total -> bsum
__global__ __launch_bounds__(256)
void scan_blk(const int* __restrict__ cnt, int* __restrict__ off, int* __restrict__ bsum)
{
    __shared__ int sh[256];
    int idx = blockIdx.x * 256 + threadIdx.x;
    int v = (idx < NNODES) ? cnt[idx] : 0;
    sh[threadIdx.x] = v;
    __syncthreads();
#pragma unroll
    for (int d = 1; d < 256; d <<= 1) {
        int t = (threadIdx.x >= d) ? sh[threadIdx.x - d] : 0;
        __syncthreads();
        sh[threadIdx.x] += t;
        __syncthreads();
    }
    if (idx < NNODES) off[idx] = sh[threadIdx.x] - v;   // exclusive within block
    if (threadIdx.x == 255) bsum[blockIdx.x] = sh[255];
}
// single-block exclusive scan of SCAN_BLKS totals
__global__ __launch_bounds__(256)
void scan_top(const int* __restrict__ bsum, int* __restrict__ boff)
{
    __shared__ int sh[256];
    int v = (threadIdx.x < SCAN_BLKS) ? bsum[threadIdx.x] : 0;
    sh[threadIdx.x] = v;
    __syncthreads();
#pragma unroll
    for (int d = 1; d < 256; d <<= 1) {
        int t = (threadIdx.x >= d) ? sh[threadIdx.x - d] : 0;
        __syncthreads();
        sh[threadIdx.x] += t;
        __syncthreads();
    }
    if (threadIdx.x < SCAN_BLKS) boff[threadIdx.x] = sh[threadIdx.x] - v;
}
// add block offsets; reset cursors; off[NNODES] = NEDGES
__global__ void scan_add(int* __restrict__ off, const int* __restrict__ boff,
                         int* __restrict__ cnt)
{
    int idx = blockIdx.x * 256 + threadIdx.x;
    if (idx < NNODES) {
        off[idx] += boff[blockIdx.x];
        cnt[idx] = 0;
    }
    if (idx == 0) off[NNODES] = NEDGES;
}
__global__ void csr_fill(const int* __restrict__ src, const int* __restrict__ dst,
                         const int* __restrict__ off, int* __restrict__ cur,
                         int* __restrict__ eid)
{
    int t = blockIdx.x * blockDim.x + threadIdx.x;
    if (t >= NEDGES) return;
    int d = __ldg(&dst[t]);
    int p = atomicAdd(&cur[d], 1);
    eid[__ldg(&off[d]) + p] = __ldg(&src[t]);
}

// ---------------- pull segment-sum (+ fused split) ----------------
__global__ __launch_bounds__(256)
void pull_sum(const float* __restrict__ h, const int* __restrict__ off,
              const int* __restrict__ eid, float* __restrict__ xc,
              __nv_bfloat16* __restrict__ xh, __nv_bfloat16* __restrict__ xl)
{
    int node = blockIdx.x * 8 + (threadIdx.x >> 5);
    if (node >= NNODES) return;
    int lane = threadIdx.x & 31;
    int s0 = __ldg(&off[node]);
    int s1 = __ldg(&off[node + 1]);
    float4 a0 = make_float4(0.f, 0.f, 0.f, 0.f), a1 = a0;
    const float4* H = (const float4*)h;
    int i = s0;
    for (; i + 1 < s1; i += 2) {
        int e0 = __ldg(&eid[i]);
        int e1 = __ldg(&eid[i + 1]);
        const float4* r0 = H + (size_t)e0 * 64 + lane * 2;
        const float4* r1 = H + (size_t)e1 * 64 + lane * 2;
        float4 v00 = __ldg(r0), v01 = __ldg(r0 + 1);
        float4 v10 = __ldg(r1), v11 = __ldg(r1 + 1);
        a0.x += v00.x; a0.y += v00.y; a0.z += v00.z; a0.w += v00.w;
        a1.x += v01.x; a1.y += v01.y; a1.z += v01.z; a1.w += v01.w;
        a0.x += v10.x; a0.y += v10.y; a0.z += v10.z; a0.w += v10.w;
        a1.x += v11.x; a1.y += v11.y; a1.z += v11.z; a1.w += v11.w;
    }
    if (i < s1) {
        int e0 = __ldg(&eid[i]);
        const float4* r0 = H + (size_t)e0 * 64 + lane * 2;
        float4 v00 = __ldg(r0), v01 = __ldg(r0 + 1);
        a0.x += v00.x; a0.y += v00.y; a0.z += v00.z; a0.w += v00.w;
        a1.x += v01.x; a1.y += v01.y; a1.z += v01.z; a1.w += v01.w;
    }
    float4* X = (float4*)xc + (size_t)node * 64 + lane * 2;
    X[0] = a0; X[1] = a1;
    float vals[8] = {a0.x, a0.y, a0.z, a0.w, a1.x, a1.y, a1.z, a1.w};
    __nv_bfloat16 hv[8], lv[8];
#pragma unroll
    for (int j = 0; j < 8; j++) {
        hv[j] = __float2bfloat16(vals[j]);
        lv[j] = __float2bfloat16(vals[j] - __bfloat162float(hv[j]));
    }
    *(uint4*)(xh + (size_t)node * HID + lane * 8) = *(uint4*)hv;
    *(uint4*)(xl + (size_t)node * HID + lane * 8) = *(uint4*)lv;
}

__global__ void gather_out(const float* __restrict__ x, const int* __restrict__ pos,
                           float4* __restrict__ out)
{
    int t = blockIdx.x * blockDim.x + threadIdx.x;
    if (t >= NROWS_LBL * 64) return;
    int r = t >> 6, c = t & 63;
    int row = __ldg(&pos[r]);
    out[t] = *(const float4*)(x + (size_t)row * HID + (c << 2));
}

// ---------------- launch ----------------
extern "C" void kernel_launch(void* const* d_in, const int* in_sizes, int n_in,
                              void* d_out, int out_size)
{
    (void)in_sizes; (void)n_in; (void)out_size;
    const float* x    = (const float*)d_in[0];
    const float* f0w  = (const float*)d_in[1];
    const float* f0b  = (const float*)d_in[2];
    const float* f1w  = (const float*)d_in[3];
    const float* f1b  = (const float*)d_in[4];
    const float* cw   = (const float*)d_in[5];
    const float* cb   = (const float*)d_in[6];
    const int*   esrc = (const int*)d_in[7];
    const int*   edst = (const int*)d_in[8];
    const int*   pos  = (const int*)d_in[9];

    float *h, *xc, *beff;
    __nv_bfloat16 *xh, *xl, *wth, *wtl;
    int *cnt, *off, *eid, *bsum, *boff;
    cudaGetSymbolAddress((void**)&h,    g_h);
    cudaGetSymbolAddress((void**)&xc,   g_x);
    cudaGetSymbolAddress((void**)&xh,   g_xh);
    cudaGetSymbolAddress((void**)&xl,   g_xl);
    cudaGetSymbolAddress((void**)&wth,  g_wth);
    cudaGetSymbolAddress((void**)&wtl,  g_wtl);
    cudaGetSymbolAddress((void**)&beff, g_beff);
    cudaGetSymbolAddress((void**)&cnt,  g_cnt);
    cudaGetSymbolAddress((void**)&off,  g_off);
    cudaGetSymbolAddress((void**)&eid,  g_eid);
    cudaGetSymbolAddress((void**)&bsum, g_bsum);
    cudaGetSymbolAddress((void**)&boff, g_boff);

    const int SMEM_DYN = 2 * STAGE_B;
    cudaFuncSetAttribute(tc_gemm, cudaFuncAttributeMaxDynamicSharedMemorySize, SMEM_DYN);

    const int n4 = NNODES * HID / 4;
    dim3 gN((NNODES + 127) / 128, 2);
    dim3 gL(NROWS_LBL / 128, 2);

    // fused weights/biases + CSR build
    fuse_w<<<dim3(256, 6), 256>>>(f0w, f1w, cw, wth, wtl);
    fuse_b<<<6, 256>>>(f0b, f1b, cw, cb, beff);
    csr_zero<<<(NNODES + 255) / 256, 256>>>(cnt);
    csr_hist<<<(NEDGES + 255) / 256, 256>>>(edst, cnt);
    scan_blk<<<SCAN_BLKS, 256>>>(cnt, off, bsum);
    scan_top<<<1, 256>>>(bsum, boff);
    scan_add<<<SCAN_BLKS, 256>>>(off, boff, cnt);
    csr_fill<<<(NEDGES + 255) / 256, 256>>>(esrc, edst, off, cnt, eid);

    to_pair<<<(n4 + 255) / 256, 256>>>(x, xh, xl, n4);

    for (int i = 0; i < 3; i++) {
        const size_t wo0 = (size_t)(i * 2 + 0) * 65536;
        const size_t wo1 = (size_t)(i * 2 + 1) * 65536;
        // h = x @ (W0·Wc) + (b0·Wc + cb)
        tc_gemm<<<gN, 256, SMEM_DYN>>>(xh, xl, wth + wo0, wtl + wo0,
                                       beff + (i * 2 + 0) * 256, h, NNODES, nullptr);
        // h[idx] = x[idx] @ (W1·Wc) + (b1·Wc + cb)
        tc_gemm<<<gL, 256, SMEM_DYN>>>(xh, xl, wth + wo1, wtl + wo1,
                                       beff + (i * 2 + 1) * 256, h, NROWS_LBL, pos);
        // x = segment_sum(h[src], dst)  + fused split
        pull_sum<<<(NNODES + 7) / 8, 256>>>(h, off, eid, xc, xh, xl);
    }
    gather_out<<<(NROWS_LBL * 64 + 255) / 256, 256>>>(xc, pos, (float4*)d_out);
}